// round 3
// baseline (speedup 1.0000x reference)
#include <cuda_runtime.h>
#include <stdint.h>

#define NN 100000
#define F  64
#define E_MAX 1700000

// ---- scratch (static __device__ arrays; no allocation allowed) ----
__device__ float g_deg[NN];
__device__ float g_dis[NN];
__device__ int   g_src[E_MAX];
__device__ int   g_dst[E_MAX];
__device__ float g_norm[E_MAX];
__device__ float g_h[NN * F];     // linear output of current layer
__device__ float g_agg[NN * F];   // layer-1 aggregation result (post-bias)
__device__ int   g_is64;          // 1 if edge_index is int64, 0 if int32

// ---------------------------------------------------------------------------
// K0: detect edge_index dtype. For nonnegative int64 (LE), every odd 32-bit
// word is 0. For random int32 indices, essentially never.
__global__ void k_detect(const unsigned int* __restrict__ w) {
    if (threadIdx.x == 0 && blockIdx.x == 0) {
        int is64 = 1;
        #pragma unroll 1
        for (int i = 1; i < 128; i += 2) {
            if (w[i] != 0u) { is64 = 0; break; }
        }
        g_is64 = is64;
    }
}

__device__ __forceinline__ int load_idx(const void* ei, long long elem, int is64) {
    if (is64) return (int)((const long long*)ei)[elem];
    return ((const int*)ei)[elem];
}

// K1: deg init (self-loop contributes 1 to every node)
__global__ void k_deg_init(float* deg, int n) {
    int i = blockIdx.x * blockDim.x + threadIdx.x;
    if (i < n) deg[i] = 1.0f;
}

// K2: deg accumulate over real edges (dst row of edge_index [2,E])
__global__ void k_deg_acc(const void* __restrict__ ei, float* deg, int E) {
    int e = blockIdx.x * blockDim.x + threadIdx.x;
    if (e >= E) return;
    int d = load_idx(ei, (long long)E + e, g_is64);
    if ((unsigned)d < (unsigned)NN) atomicAdd(&deg[d], 1.0f);
}

// K3: dis = deg^{-1/2}  (deg >= 1 always due to self-loop)
__global__ void k_dis(const float* __restrict__ deg, float* dis, int n) {
    int i = blockIdx.x * blockDim.x + threadIdx.x;
    if (i < n) dis[i] = rsqrtf(deg[i]);
}

// K4: pack edges to int32 and precompute per-edge norm (reused by both layers)
__global__ void k_pack(const void* __restrict__ ei, const float* __restrict__ dis,
                       int* __restrict__ src, int* __restrict__ dst,
                       float* __restrict__ nrm, int E) {
    int e = blockIdx.x * blockDim.x + threadIdx.x;
    if (e >= E) return;
    int is64 = g_is64;
    int s = load_idx(ei, e, is64);
    int d = load_idx(ei, (long long)E + e, is64);
    if ((unsigned)s >= (unsigned)NN || (unsigned)d >= (unsigned)NN) {
        src[e] = 0; dst[e] = 0; nrm[e] = 0.0f;   // defensive: never crash
        return;
    }
    src[e] = s;
    dst[e] = d;
    nrm[e] = dis[s] * dis[d];
}

// ---------------------------------------------------------------------------
// GEMM: H[n,64] = act(X[n,64]) @ W[64,64].  Warp-per-row, W in smem,
// x row held in registers (float2/lane), broadcast via shfl.
__global__ void k_gemm64(const float* __restrict__ X, const float* __restrict__ Wg,
                         float* __restrict__ H, int n, int do_relu) {
    __shared__ __align__(16) float Ws[F * F];
    for (int i = threadIdx.x; i < F * F; i += blockDim.x) Ws[i] = Wg[i];
    __syncthreads();

    int warp = (blockIdx.x * blockDim.x + threadIdx.x) >> 5;
    int lane = threadIdx.x & 31;
    if (warp >= n) return;

    float2 xv = ((const float2*)(X + (size_t)warp * F))[lane];
    if (do_relu) { xv.x = fmaxf(xv.x, 0.0f); xv.y = fmaxf(xv.y, 0.0f); }

    float a0 = 0.0f, a1 = 0.0f;
#pragma unroll
    for (int k = 0; k < F; k++) {
        float xk = __shfl_sync(0xffffffffu, (k & 1) ? xv.y : xv.x, k >> 1);
        float2 w = ((const float2*)(Ws + k * F))[lane];
        a0 = fmaf(xk, w.x, a0);
        a1 = fmaf(xk, w.y, a1);
    }
    ((float2*)(H + (size_t)warp * F))[lane] = make_float2(a0, a1);
}

// ---------------------------------------------------------------------------
// Aggregation init: Agg[i,:] = H[i,:] * dis[i]^2 + b[:]
// (folds the self-loop message AND the bias; also initializes the buffer,
//  which for layer 2 is d_out that arrives poisoned)
__global__ void k_init_agg(const float* __restrict__ H, const float* __restrict__ dis,
                           const float* __restrict__ b, float* __restrict__ Agg, int n) {
    int idx = blockIdx.x * blockDim.x + threadIdx.x;   // n*32 float2 slots
    if (idx >= n * 32) return;
    int node = idx >> 5, pair = idx & 31;
    float d  = dis[node];
    float sl = d * d;
    float2 h  = ((const float2*)H)[(size_t)node * 32 + pair];
    float2 bb = ((const float2*)b)[pair];
    ((float2*)Agg)[(size_t)node * 32 + pair] = make_float2(fmaf(h.x, sl, bb.x),
                                                           fmaf(h.y, sl, bb.y));
}

// ---------------------------------------------------------------------------
// Edge scatter: warp per edge.  Gather 256B row of H[src], scale by norm,
// RED.F32-add into Agg[dst].
__global__ void k_scatter(const int* __restrict__ src, const int* __restrict__ dst,
                          const float* __restrict__ nrm, const float* __restrict__ H,
                          float* __restrict__ Agg, int E) {
    int gw   = (blockIdx.x * blockDim.x + threadIdx.x) >> 5;
    int lane = threadIdx.x & 31;
    if (gw >= E) return;
    int   s  = src[gw];
    int   d  = dst[gw];
    float nm = nrm[gw];
    float2 v = ((const float2*)(H + (size_t)s * F))[lane];
    float* out = Agg + (size_t)d * F + lane * 2;
    atomicAdd(out,     v.x * nm);
    atomicAdd(out + 1, v.y * nm);
}

// ---------------------------------------------------------------------------
static inline int cdiv(int a, int b) { return (a + b - 1) / b; }

extern "C" void kernel_launch(void* const* d_in, const int* in_sizes, int n_in,
                              void* d_out, int out_size) {
    const float* x  = (const float*)d_in[0];
    const void*  ei = d_in[1];
    const float* W1 = (const float*)d_in[2];
    const float* b1 = (const float*)d_in[3];
    const float* W2 = (const float*)d_in[4];
    const float* b2 = (const float*)d_in[5];
    float*       out = (float*)d_out;

    const int N = in_sizes[0] / F;        // 100000
    const int E = in_sizes[1] / 2;        // 1600000

    float *deg, *dis, *nrm, *h, *agg;
    int *src, *dst;
    cudaGetSymbolAddress((void**)&deg, g_deg);
    cudaGetSymbolAddress((void**)&dis, g_dis);
    cudaGetSymbolAddress((void**)&src, g_src);
    cudaGetSymbolAddress((void**)&dst, g_dst);
    cudaGetSymbolAddress((void**)&nrm, g_norm);
    cudaGetSymbolAddress((void**)&h,   g_h);
    cudaGetSymbolAddress((void**)&agg, g_agg);

    const int T = 256;

    // dtype detect + degree + normalization
    k_detect  <<<1, 32>>>((const unsigned int*)ei);
    k_deg_init<<<cdiv(N, T), T>>>(deg, N);
    k_deg_acc <<<cdiv(E, T), T>>>(ei, deg, E);
    k_dis     <<<cdiv(N, T), T>>>(deg, dis, N);
    k_pack    <<<cdiv(E, T), T>>>(ei, dis, src, dst, nrm, E);

    // ---- layer 1 ----
    k_gemm64  <<<cdiv(N * 32, T), T>>>(x, W1, h, N, 0);          // h = x @ W1
    k_init_agg<<<cdiv(N * 32, T), T>>>(h, dis, b1, agg, N);      // self-loop + bias
    k_scatter <<<cdiv(E * 32, T), T>>>(src, dst, nrm, h, agg, E);

    // ---- layer 2 ----
    k_gemm64  <<<cdiv(N * 32, T), T>>>(agg, W2, h, N, 1);        // h = relu(agg) @ W2
    k_init_agg<<<cdiv(N * 32, T), T>>>(h, dis, b2, out, N);      // writes d_out fully
    k_scatter <<<cdiv(E * 32, T), T>>>(src, dst, nrm, h, out, E);
}

// round 5
// speedup vs baseline: 1.4042x; 1.4042x over previous
#include <cuda_runtime.h>
#include <stdint.h>

#define NN 100000
#define F  64
#define E_MAX 1700000

// ---- scratch (static __device__ arrays; no allocation allowed) ----
__device__ float g_deg[NN];
__device__ float g_dis[NN];
__device__ int   g_src[E_MAX];
__device__ int   g_dst[E_MAX];
__device__ float g_norm[E_MAX];
__device__ float g_h[NN * F];     // linear output of current layer
__device__ float g_agg[NN * F];   // layer-1 aggregation result (post-bias)
__device__ int   g_is64;          // 1 if edge_index is int64, 0 if int32

// ---------------------------------------------------------------------------
// K0: detect edge_index dtype. For nonnegative int64 (LE), every odd 32-bit
// word is 0. For random int32 indices, essentially never.
__global__ void k_detect(const unsigned int* __restrict__ w) {
    if (threadIdx.x == 0 && blockIdx.x == 0) {
        int is64 = 1;
        #pragma unroll 1
        for (int i = 1; i < 128; i += 2) {
            if (w[i] != 0u) { is64 = 0; break; }
        }
        g_is64 = is64;
    }
}

__device__ __forceinline__ int load_idx(const void* ei, long long elem, int is64) {
    if (is64) return (int)((const long long*)ei)[elem];
    return ((const int*)ei)[elem];
}

// K1: deg init (self-loop contributes 1 to every node)
__global__ void k_deg_init(float* deg, int n) {
    int i = blockIdx.x * blockDim.x + threadIdx.x;
    if (i < n) deg[i] = 1.0f;
}

// K2: deg accumulate over real edges (dst row of edge_index [2,E])
__global__ void k_deg_acc(const void* __restrict__ ei, float* deg, int E) {
    int e = blockIdx.x * blockDim.x + threadIdx.x;
    if (e >= E) return;
    int d = load_idx(ei, (long long)E + e, g_is64);
    if ((unsigned)d < (unsigned)NN) atomicAdd(&deg[d], 1.0f);
}

// K3: dis = deg^{-1/2}  (deg >= 1 always due to self-loop)
__global__ void k_dis(const float* __restrict__ deg, float* dis, int n) {
    int i = blockIdx.x * blockDim.x + threadIdx.x;
    if (i < n) dis[i] = rsqrtf(deg[i]);
}

// K4: pack edges to int32 and precompute per-edge norm (reused by both layers)
__global__ void k_pack(const void* __restrict__ ei, const float* __restrict__ dis,
                       int* __restrict__ src, int* __restrict__ dst,
                       float* __restrict__ nrm, int E) {
    int e = blockIdx.x * blockDim.x + threadIdx.x;
    if (e >= E) return;
    int is64 = g_is64;
    int s = load_idx(ei, e, is64);
    int d = load_idx(ei, (long long)E + e, is64);
    if ((unsigned)s >= (unsigned)NN || (unsigned)d >= (unsigned)NN) {
        src[e] = 0; dst[e] = 0; nrm[e] = 0.0f;   // defensive: never crash
        return;
    }
    src[e] = s;
    dst[e] = d;
    nrm[e] = dis[s] * dis[d];
}

// ---------------------------------------------------------------------------
// Fused GEMM + aggregation init.
//   H[row]   = act(X[row]) @ W
//   Agg[row] = H[row] * dis[row]^2 + b        (self-loop msg + bias + buffer init)
// Warp-per-row, W in smem, x row in registers (float2/lane), shfl broadcast.
__global__ void k_gemm64(const float* __restrict__ X, const float* __restrict__ Wg,
                         const float* __restrict__ dis, const float* __restrict__ b,
                         float* __restrict__ H, float* __restrict__ Agg,
                         int n, int do_relu) {
    __shared__ __align__(16) float Ws[F * F];
    for (int i = threadIdx.x; i < F * F; i += blockDim.x) Ws[i] = Wg[i];
    __syncthreads();

    int warp = (blockIdx.x * blockDim.x + threadIdx.x) >> 5;
    int lane = threadIdx.x & 31;
    if (warp >= n) return;

    float2 xv = ((const float2*)(X + (size_t)warp * F))[lane];
    if (do_relu) { xv.x = fmaxf(xv.x, 0.0f); xv.y = fmaxf(xv.y, 0.0f); }

    float a0 = 0.0f, a1 = 0.0f;
#pragma unroll
    for (int k = 0; k < F; k++) {
        float xk = __shfl_sync(0xffffffffu, (k & 1) ? xv.y : xv.x, k >> 1);
        float2 w = ((const float2*)(Ws + k * F))[lane];
        a0 = fmaf(xk, w.x, a0);
        a1 = fmaf(xk, w.y, a1);
    }

    float dd = dis[warp];
    float sl = dd * dd;
    float2 bb = ((const float2*)b)[lane];
    ((float2*)(H   + (size_t)warp * F))[lane] = make_float2(a0, a1);
    ((float2*)(Agg + (size_t)warp * F))[lane] = make_float2(fmaf(a0, sl, bb.x),
                                                            fmaf(a1, sl, bb.y));
}

// ---------------------------------------------------------------------------
// Edge scatter: 16 lanes per edge (warp covers 2 edges). Gather the 256B row
// of H[src] as float4s, scale by norm, vector-reduce into Agg[dst] with
// red.global.add.v4.f32 (4x fewer atomic ops than scalar).
__global__ void k_scatter(const int* __restrict__ src, const int* __restrict__ dst,
                          const float* __restrict__ nrm, const float* __restrict__ H,
                          float* __restrict__ Agg, int E) {
    int gw   = (blockIdx.x * blockDim.x + threadIdx.x) >> 5;
    int lane = threadIdx.x & 31;
    int sub  = lane >> 4;          // which edge within the warp
    int l16  = lane & 15;          // float4 slot within the row
    int e = gw * 2 + sub;
    if (e >= E) return;

    int   s  = src[e];
    int   d  = dst[e];
    float nm = nrm[e];
    float4 v = ((const float4*)(H + (size_t)s * F))[l16];
    float* out = Agg + (size_t)d * F + l16 * 4;
    asm volatile("red.global.add.v4.f32 [%0], {%1, %2, %3, %4};"
                 :: "l"(out), "f"(v.x * nm), "f"(v.y * nm),
                    "f"(v.z * nm), "f"(v.w * nm)
                 : "memory");
}

// ---------------------------------------------------------------------------
static inline int cdiv(int a, int b) { return (a + b - 1) / b; }

extern "C" void kernel_launch(void* const* d_in, const int* in_sizes, int n_in,
                              void* d_out, int out_size) {
    const float* x  = (const float*)d_in[0];
    const void*  ei = d_in[1];
    const float* W1 = (const float*)d_in[2];
    const float* b1 = (const float*)d_in[3];
    const float* W2 = (const float*)d_in[4];
    const float* b2 = (const float*)d_in[5];
    float*       out = (float*)d_out;

    const int N = in_sizes[0] / F;        // 100000
    const int E = in_sizes[1] / 2;        // 1600000

    float *deg, *dis, *nrm, *h, *agg;
    int *src, *dst;
    cudaGetSymbolAddress((void**)&deg, g_deg);
    cudaGetSymbolAddress((void**)&dis, g_dis);
    cudaGetSymbolAddress((void**)&src, g_src);
    cudaGetSymbolAddress((void**)&dst, g_dst);
    cudaGetSymbolAddress((void**)&nrm, g_norm);
    cudaGetSymbolAddress((void**)&h,   g_h);
    cudaGetSymbolAddress((void**)&agg, g_agg);

    const int T = 256;
    const int scatter_blocks = cdiv(cdiv(E, 2) * 32, T);

    // dtype detect + degree + normalization
    k_detect  <<<1, 32>>>((const unsigned int*)ei);
    k_deg_init<<<cdiv(N, T), T>>>(deg, N);
    k_deg_acc <<<cdiv(E, T), T>>>(ei, deg, E);
    k_dis     <<<cdiv(N, T), T>>>(deg, dis, N);
    k_pack    <<<cdiv(E, T), T>>>(ei, dis, src, dst, nrm, E);

    // ---- layer 1 ----  h = x @ W1;  agg = h*dis^2 + b1;  agg += scatter
    k_gemm64  <<<cdiv(N * 32, T), T>>>(x, W1, dis, b1, h, agg, N, 0);
    k_scatter <<<scatter_blocks, T>>>(src, dst, nrm, h, agg, E);

    // ---- layer 2 ----  h = relu(agg) @ W2;  out = h*dis^2 + b2;  out += scatter
    k_gemm64  <<<cdiv(N * 32, T), T>>>(agg, W2, dis, b2, h, out, N, 1);
    k_scatter <<<scatter_blocks, T>>>(src, dst, nrm, h, out, E);
}